// round 15
// baseline (speedup 1.0000x reference)
#include <cuda_runtime.h>
#include <cstdint>
#include <math.h>

// ---------------- problem constants ----------------
#define Bn   32
#define Sn   128
#define HDn  64
#define NHn  4
#define NENCn 2
#define En   8
#define NLn  4
#define CHn  32
#define Hn   128
#define Wn   128
#define PCHn 128
#define KXn  32

// ---------------- device scratch ----------------
__device__ float  g_h  [Bn*Sn*HDn];
__device__ float  g_att[Bn*Sn*HDn];
__device__ int    g_idx[Bn];
__device__ float  g_v[Bn*CHn*Hn*Wn];          // 64 MB activation
__device__ float2 g_FXY[Bn*KXn*16];           // 2D partial DFT of x [b][kx][ky]
__device__ float2 g_X[Bn*KXn*16*CHn];         // fwd coeffs [b][kx][ky][c]
__device__ float2 g_Y[Bn*CHn*KXn*16];         // mixed [b][o][kx][ky]
__device__ float2 g_Z[Bn*CHn*Hn*16];          // inv h-DFT [b][o][h][ky]
__device__ float  g_Tw[32*128];               // irfft-w twiddles (31 rows) + ones row

__device__ __forceinline__ float gelu_tanh(float x) {
    float x3 = x*x*x;
    float z  = 0.7978845608028654f*(x + 0.044715f*x3);
    float t  = 1.0f - 2.0f/(__expf(2.0f*z) + 1.0f);
    return 0.5f*x*(1.0f + t);
}

// ========================= init: twiddle table =========================
__global__ void k_tw() {
    int k = blockIdx.x, w = threadIdx.x;
    float val;
    if (k == 0)       val = 1.0f;
    else if (k < 16)  { int t = (k*w) & 127;      val = cosf(0.0490873852123405f*(float)t); }
    else if (k < 31)  { int t = ((k-15)*w) & 127; val = sinf(0.0490873852123405f*(float)t); }
    else              val = 1.0f;
    g_Tw[k*128 + w] = val;
}

// ========================= ROUTER =========================

__global__ void k_encode(const float* __restrict__ x,
                         const float* __restrict__ w,
                         const float* __restrict__ b) {
    int i = blockIdx.x*blockDim.x + threadIdx.x;
    const int tot = Bn*Sn*HDn;
    for (; i < tot; i += gridDim.x*blockDim.x) {
        int d = i & 63;
        int s = (i >> 6) & 127;
        int bb = i >> 13;
        g_h[i] = x[bb*(Hn*Wn) + s]*w[d] + b[d];
    }
}

// fused qkv + flash attention, 2-way split softmax; block = (b, head), 256 threads
__global__ __launch_bounds__(256) void k_attn_qkv(const float* __restrict__ qw,
                                                  const float* __restrict__ qb, int l) {
    __shared__ float buf[11264];
    int b = blockIdx.x >> 2, hd = blockIdx.x & 3;
    int tid = threadIdx.x;
    int i = tid & 127, half = tid >> 7;

    float* hs = buf;
    float* Ws = buf + 8192;
    for (int p = tid; p < 2048; p += 256)
        ((float4*)hs)[p] = ((const float4*)(g_h + b*8192))[p];
    {
        const float* W = qw + l*64*192;
        for (int p = tid; p < 3072; p += 256) {
            int d = p/48, c = p - d*48;
            int gc = hd*16 + (c & 15) + (c >> 4)*64;
            Ws[p] = W[d*192 + gc];
        }
    }
    __syncthreads();

    float q[16], kv[16];
    {
        const float* qbl = qb + l*192 + hd*16;
        int kvoff = half ? 128 : 64;
        #pragma unroll
        for (int j = 0; j < 16; j++) { q[j] = qbl[j]; kv[j] = qbl[kvoff + j]; }
        int woff = half ? 8 : 4;
        for (int d = 0; d < 64; d++) {
            float hv = hs[i*64 + d];
            const float4* wr = (const float4*)(Ws + d*48);
            #pragma unroll
            for (int jj = 0; jj < 4; jj++) {
                float4 wq = wr[jj], wk = wr[woff + jj];
                q [jj*4+0] += hv*wq.x; q [jj*4+1] += hv*wq.y; q [jj*4+2] += hv*wq.z; q [jj*4+3] += hv*wq.w;
                kv[jj*4+0] += hv*wk.x; kv[jj*4+1] += hv*wk.y; kv[jj*4+2] += hv*wk.z; kv[jj*4+3] += hv*wk.w;
            }
        }
    }
    __syncthreads();

    float* ks   = buf;
    float* vs   = buf + 2048;
    float* mArr = buf + 4096;
    float* sArr = buf + 4352;
    float* oArr = buf + 4608;
    {
        float* dst = (half ? vs : ks) + i*16;
        #pragma unroll
        for (int j = 0; j < 16; j++) dst[j] = kv[j];
    }
    __syncthreads();

    int j0 = half*64;
    float m = -1e30f, ssum = 0.f;
    float out[16];
    #pragma unroll
    for (int d = 0; d < 16; d++) out[d] = 0.f;
    for (int jj = 0; jj < 64; jj += 4) {
        float s[4];
        #pragma unroll
        for (int r = 0; r < 4; r++) {
            const float4* kr = (const float4*)(ks + (j0 + jj + r)*16);
            float4 a0 = kr[0], a1 = kr[1], a2 = kr[2], a3 = kr[3];
            float p0 = q[0]*a0.x  + q[1]*a0.y  + q[2]*a0.z  + q[3]*a0.w;
            float p1 = q[4]*a1.x  + q[5]*a1.y  + q[6]*a1.z  + q[7]*a1.w;
            float p2 = q[8]*a2.x  + q[9]*a2.y  + q[10]*a2.z + q[11]*a2.w;
            float p3 = q[12]*a3.x + q[13]*a3.y + q[14]*a3.z + q[15]*a3.w;
            s[r] = ((p0 + p1) + (p2 + p3))*0.25f;
        }
        float mn = fmaxf(m, fmaxf(fmaxf(s[0], s[1]), fmaxf(s[2], s[3])));
        float corr = __expf(m - mn);
        float w0 = __expf(s[0] - mn), w1 = __expf(s[1] - mn);
        float w2 = __expf(s[2] - mn), w3 = __expf(s[3] - mn);
        ssum = ssum*corr + ((w0 + w1) + (w2 + w3));
        #pragma unroll
        for (int d = 0; d < 16; d++) out[d] *= corr;
        {
            const float4* v0 = (const float4*)(vs + (j0 + jj    )*16);
            const float4* v1 = (const float4*)(vs + (j0 + jj + 1)*16);
            const float4* v2 = (const float4*)(vs + (j0 + jj + 2)*16);
            const float4* v3 = (const float4*)(vs + (j0 + jj + 3)*16);
            #pragma unroll
            for (int g4 = 0; g4 < 4; g4++) {
                float4 b0 = v0[g4], b1 = v1[g4], b2 = v2[g4], b3 = v3[g4];
                out[g4*4+0] += w0*b0.x + w1*b1.x + w2*b2.x + w3*b3.x;
                out[g4*4+1] += w0*b0.y + w1*b1.y + w2*b2.y + w3*b3.y;
                out[g4*4+2] += w0*b0.z + w1*b1.z + w2*b2.z + w3*b3.z;
                out[g4*4+3] += w0*b0.w + w1*b1.w + w2*b2.w + w3*b3.w;
            }
        }
        m = mn;
    }
    mArr[tid] = m; sArr[tid] = ssum;
    {
        float* od = oArr + tid*16;
        #pragma unroll
        for (int d = 0; d < 16; d++) od[d] = out[d];
    }
    __syncthreads();

    if (half == 0) {
        float m1 = mArr[128 + i], s1v = sArr[128 + i];
        float M  = fmaxf(m, m1);
        float c0 = __expf(m - M), c1 = __expf(m1 - M);
        float inv = 1.0f/(ssum*c0 + s1v*c1);
        const float* o1 = oArr + (128 + i)*16;
        float* ob = g_att + (b*128 + i)*64 + hd*16;
        #pragma unroll
        for (int d = 0; d < 16; d++) ob[d] = (out[d]*c0 + o1[d]*c1)*inv;
    }
}

// fused: h = LN1(h + att@ao + ab); h = LN2(h + relu(h@W1+b1)@W2 + b2)
__global__ __launch_bounds__(256) void k_plf(
        const float* __restrict__ aw, const float* __restrict__ ab,
        const float* __restrict__ lns, const float* __restrict__ lnb,
        const float* __restrict__ w1, const float* __restrict__ b1,
        const float* __restrict__ w2, const float* __restrict__ b2,
        const float* __restrict__ ln2s, const float* __restrict__ ln2b, int l) {
    __shared__ float as_[1024], ts[1024], hs[1024];
    __shared__ float hid[4096];
    __shared__ float red[4096];
    int row0 = blockIdx.x*16;
    int tid = threadIdx.x;
    int warp = tid >> 5, lane = tid & 31;

    for (int p = tid; p < 1024; p += 256) as_[p] = g_att[row0*64 + p];
    __syncthreads();
    {
        const float* wl = aw + l*4096;
        int dq = tid & 15, rq = (tid >> 4) & 3, js = tid >> 6;
        int d0 = dq*4, r0 = rq*4, e0 = js*16;
        float acc[4][4];
        #pragma unroll
        for (int rr = 0; rr < 4; rr++)
            #pragma unroll
            for (int dd = 0; dd < 4; dd++) acc[rr][dd] = 0.f;
        #pragma unroll 4
        for (int ee = 0; ee < 16; ee++) {
            int eidx = e0 + ee;
            float4 wv = *(const float4*)(wl + eidx*64 + d0);
            #pragma unroll
            for (int rr = 0; rr < 4; rr++) {
                float hv = as_[(r0+rr)*64 + eidx];
                acc[rr][0] += hv*wv.x; acc[rr][1] += hv*wv.y;
                acc[rr][2] += hv*wv.z; acc[rr][3] += hv*wv.w;
            }
        }
        #pragma unroll
        for (int rr = 0; rr < 4; rr++)
            #pragma unroll
            for (int dd = 0; dd < 4; dd++)
                red[js*1024 + (r0+rr)*64 + d0+dd] = acc[rr][dd];
    }
    __syncthreads();
    for (int p = tid; p < 1024; p += 256) {
        int r = p >> 6, d = p & 63;
        ts[p] = red[p] + red[1024+p] + red[2048+p] + red[3072+p]
              + g_h[(row0+r)*64 + d] + ab[l*64 + d];
    }
    __syncthreads();
    {
        const float* s_ = lns + l*64; const float* b_ = lnb + l*64;
        #pragma unroll
        for (int rr = 0; rr < 2; rr++) {
            int r = warp*2 + rr;
            float a = ts[r*64+lane], bv = ts[r*64+32+lane];
            float s = a + bv, qq = a*a + bv*bv;
            #pragma unroll
            for (int off = 16; off > 0; off >>= 1) {
                s  += __shfl_xor_sync(0xffffffff, s,  off);
                qq += __shfl_xor_sync(0xffffffff, qq, off);
            }
            float mu = s*(1.0f/64.0f);
            float var = qq*(1.0f/64.0f) - mu*mu;
            float rs = rsqrtf(var + 1e-5f);
            hs[r*64+lane]    = (a  - mu)*rs*s_[lane]    + b_[lane];
            hs[r*64+32+lane] = (bv - mu)*rs*s_[32+lane] + b_[32+lane];
        }
    }
    __syncthreads();
    {
        const float* W1 = w1 + l*16384;
        int rq = tid >> 6, jg = tid & 63;
        int j0 = jg*4;
        float4 bv = *(const float4*)(b1 + l*256 + j0);
        float acc[4][4];
        #pragma unroll
        for (int rr = 0; rr < 4; rr++) {
            acc[rr][0]=bv.x; acc[rr][1]=bv.y; acc[rr][2]=bv.z; acc[rr][3]=bv.w;
        }
        #pragma unroll 4
        for (int d = 0; d < 64; d++) {
            float4 wv = *(const float4*)(W1 + d*256 + j0);
            #pragma unroll
            for (int rr = 0; rr < 4; rr++) {
                float hv = hs[(rq*4+rr)*64 + d];
                acc[rr][0] += hv*wv.x; acc[rr][1] += hv*wv.y;
                acc[rr][2] += hv*wv.z; acc[rr][3] += hv*wv.w;
            }
        }
        #pragma unroll
        for (int rr = 0; rr < 4; rr++)
            #pragma unroll
            for (int jj = 0; jj < 4; jj++)
                hid[(rq*4+rr)*256 + j0 + jj] = fmaxf(acc[rr][jj], 0.0f);
    }
    __syncthreads();
    {
        const float* W2 = w2 + l*16384;
        int dq = tid & 15, rq = (tid >> 4) & 3, js = tid >> 6;
        int d0 = dq*4, r0 = rq*4, j0 = js*64;
        float acc[4][4];
        #pragma unroll
        for (int rr = 0; rr < 4; rr++)
            #pragma unroll
            for (int dd = 0; dd < 4; dd++) acc[rr][dd] = 0.f;
        #pragma unroll 4
        for (int jj = 0; jj < 64; jj++) {
            int j = j0 + jj;
            float4 wv = *(const float4*)(W2 + j*64 + d0);
            #pragma unroll
            for (int rr = 0; rr < 4; rr++) {
                float hv = hid[(r0+rr)*256 + j];
                acc[rr][0] += hv*wv.x; acc[rr][1] += hv*wv.y;
                acc[rr][2] += hv*wv.z; acc[rr][3] += hv*wv.w;
            }
        }
        #pragma unroll
        for (int rr = 0; rr < 4; rr++)
            #pragma unroll
            for (int dd = 0; dd < 4; dd++)
                red[js*1024 + (r0+rr)*64 + d0+dd] = acc[rr][dd];
    }
    __syncthreads();
    for (int p = tid; p < 1024; p += 256) {
        int d = p & 63;
        ts[p] = red[p] + red[1024+p] + red[2048+p] + red[3072+p] + hs[p] + b2[l*64+d];
    }
    __syncthreads();
    {
        const float* s_ = ln2s + l*64; const float* b_ = ln2b + l*64;
        #pragma unroll
        for (int rr = 0; rr < 2; rr++) {
            int r = warp*2 + rr;
            float a = ts[r*64+lane], bv = ts[r*64+32+lane];
            float s = a + bv, qq = a*a + bv*bv;
            #pragma unroll
            for (int off = 16; off > 0; off >>= 1) {
                s  += __shfl_xor_sync(0xffffffff, s,  off);
                qq += __shfl_xor_sync(0xffffffff, qq, off);
            }
            float mu = s*(1.0f/64.0f);
            float var = qq*(1.0f/64.0f) - mu*mu;
            float rs = rsqrtf(var + 1e-5f);
            g_h[(row0+r)*64+lane]    = (a  - mu)*rs*s_[lane]    + b_[lane];
            g_h[(row0+r)*64+32+lane] = (bv - mu)*rs*s_[32+lane] + b_[32+lane];
        }
    }
}

__global__ __launch_bounds__(128) void k_head(const float* __restrict__ fcw,
                                              const float* __restrict__ fcb) {
    __shared__ float fe[128];
    int b = blockIdx.x;
    int t = threadIdx.x;
    int d = t & 63, sh = t >> 6;
    float acc = 0.f;
    for (int s = sh*64; s < sh*64 + 64; s++) acc += g_h[(b*128+s)*64 + d];
    fe[t] = acc;
    __syncthreads();
    if (t < 64) fe[t] = (fe[t] + fe[t+64])*(1.0f/128.0f);
    __syncthreads();
    if (t == 0) {
        float best = -1e30f; int bi = 0;
        for (int e = 0; e < En; e++) {
            float a = fcb[e];
            for (int dd = 0; dd < 64; dd++) a += fe[dd]*fcw[dd*En + e];
            if (a > best) { best = a; bi = e; }
        }
        g_idx[b] = bi;
    }
}

// ========================= FNO =========================

__global__ __launch_bounds__(256) void k_lift(const float* __restrict__ x,
                                              const float* __restrict__ lw,
                                              const float* __restrict__ lb) {
    __shared__ float xr[128];
    __shared__ float ws[32], bs[32];
    int bb = blockIdx.x >> 7, h = blockIdx.x & 127;
    int e = g_idx[bb];
    if (threadIdx.x < 128) xr[threadIdx.x] = x[bb*16384 + h*128 + threadIdx.x];
    if (threadIdx.x < 32) { ws[threadIdx.x] = lw[e*32+threadIdx.x]; bs[threadIdx.x] = lb[e*32+threadIdx.x]; }
    __syncthreads();
    for (int p = threadIdx.x; p < 4096; p += 256) {
        int d = p >> 7, w = p & 127;
        g_v[((bb*32+d)*128 + h)*128 + w] = xr[w]*ws[d] + bs[d];
    }
}

// 2D partial DFT of the single-channel input x, per b (layer-0 shortcut)
__global__ __launch_bounds__(256) void k_fxy(const float* __restrict__ x) {
    extern __shared__ float sm[];
    float*  vs = sm;
    float2* Az = (float2*)(sm + 8448);
    float*  Tc = sm + 8448 + 4096;
    float*  Ts = Tc + 1024;
    float*  ct = Ts + 1024;
    float*  st = ct + 128;
    int bb = blockIdx.x;
    int tid = threadIdx.x;
    if (tid < 128) {
        float ang = 6.283185307179586f*(float)tid/128.0f;
        ct[tid] = cosf(ang); st[tid] = sinf(ang);
    }
    for (int p = tid; p < 1024; p += 256) {
        int w = p >> 4, k = p & 15;
        int t = (w*k) & 127;
        float ang = 0.0490873852123405f*(float)t;
        Tc[p] = cosf(ang); Ts[p] = sinf(ang);
    }
    const float* vg = x + bb*16384;
    int hl = tid >> 2, kq = tid & 3, ky0 = kq*4;
    for (int half = 0; half < 2; half++) {
        __syncthreads();
        for (int p = tid; p < 2048; p += 256) {
            int r = p >> 5, q = p & 31;
            ((float4*)(vs + r*132))[q] = ((const float4*)(vg + (half*64 + r)*128))[q];
        }
        __syncthreads();
        const float* vr = vs + hl*132;
        float v0 = vr[0], v64 = vr[64];
        float re[4], im[4];
        #pragma unroll
        for (int j = 0; j < 4; j++) {
            re[j] = v0 + (((ky0+j) & 1) ? -v64 : v64);
            im[j] = 0.f;
        }
        #pragma unroll 7
        for (int w = 1; w < 64; w++) {
            float a = vr[w], b = vr[128-w];
            float s_ = a + b, d_ = a - b;
            float4 c4 = *(const float4*)(Tc + w*16 + ky0);
            float4 s4 = *(const float4*)(Ts + w*16 + ky0);
            re[0] += s_*c4.x; im[0] -= d_*s4.x;
            re[1] += s_*c4.y; im[1] -= d_*s4.y;
            re[2] += s_*c4.z; im[2] -= d_*s4.z;
            re[3] += s_*c4.w; im[3] -= d_*s4.w;
        }
        #pragma unroll
        for (int j = 0; j < 4; j++)
            Az[(half*64 + hl)*16 + ky0 + j] = make_float2(re[j], im[j]);
    }
    __syncthreads();
    int g = tid >> 4, ky = tid & 15;
    if (g == 0) {
        float rex=0.f, imx=0.f, re16=0.f, im16=0.f;
        int t = 0;
        for (int h = 0; h < 128; h++) {
            float2 a = Az[h*16 + ky];
            rex += a.x; imx += a.y;
            float cc = ct[t], ss = st[t];
            re16 += a.x*cc - a.y*ss;
            im16 += a.y*cc + a.x*ss;
            t = (t + 16) & 127;
        }
        g_FXY[(bb*32 + 0 )*16 + ky] = make_float2(rex,  imx);
        g_FXY[(bb*32 + 16)*16 + ky] = make_float2(re16, im16);
    } else {
        float u=0.f, v=0.f, pp=0.f, qq=0.f;
        int t = 0;
        for (int h = 0; h < 128; h++) {
            float2 a = Az[h*16 + ky];
            float cc = ct[t], ss = st[t];
            u  += a.x*cc; qq += a.x*ss;
            pp += a.y*cc; v  += a.y*ss;
            t = (t + g) & 127;
        }
        g_FXY[(bb*32 + g     )*16 + ky] = make_float2(u+v, pp-qq);
        g_FXY[(bb*32 + (32-g))*16 + ky] = make_float2(u-v, pp+qq);
    }
}

// layer-0 X expansion
__global__ __launch_bounds__(256) void k_x0(const float* __restrict__ lw,
                                            const float* __restrict__ lb) {
    __shared__ float ws[32], bs[32];
    __shared__ float2 fx[512];
    int bb = blockIdx.x;
    int e = g_idx[bb];
    int tid = threadIdx.x;
    if (tid < 32) { ws[tid] = lw[e*32+tid]; bs[tid] = lb[e*32+tid]; }
    for (int p = tid; p < 512; p += 256) fx[p] = g_FXY[bb*512 + p];
    __syncthreads();
    for (int p = tid; p < 16384; p += 256) {
        int c = p & 31, rest = p >> 5;
        float2 f = fx[rest];
        float2 o = make_float2(ws[c]*f.x, ws[c]*f.y);
        if (rest == 0) o.x += 16384.0f*bs[c];
        g_X[(bb*512 + rest)*32 + c] = o;
    }
}

// fused 2D forward partial DFT per (b,c) — layers 1..3
__global__ __launch_bounds__(256) void k_dft2() {
    extern __shared__ float sm[];
    float*  vs = sm;
    float2* Az = (float2*)(sm + 8448);
    float*  Tc = sm + 8448 + 4096;
    float*  Ts = Tc + 1024;
    float*  ct = Ts + 1024;
    float*  st = ct + 128;
    int bb = blockIdx.x >> 5, c = blockIdx.x & 31;
    int tid = threadIdx.x;
    if (tid < 128) {
        float ang = 6.283185307179586f*(float)tid/128.0f;
        ct[tid] = cosf(ang); st[tid] = sinf(ang);
    }
    for (int p = tid; p < 1024; p += 256) {
        int w = p >> 4, k = p & 15;
        int t = (w*k) & 127;
        float ang = 0.0490873852123405f*(float)t;
        Tc[p] = cosf(ang); Ts[p] = sinf(ang);
    }
    const float* vg = g_v + (bb*32 + c)*16384;
    int hl = tid >> 2, kq = tid & 3, ky0 = kq*4;
    for (int half = 0; half < 2; half++) {
        __syncthreads();
        for (int p = tid; p < 2048; p += 256) {
            int r = p >> 5, q = p & 31;
            ((float4*)(vs + r*132))[q] = ((const float4*)(vg + (half*64 + r)*128))[q];
        }
        __syncthreads();
        const float* vr = vs + hl*132;
        float v0 = vr[0], v64 = vr[64];
        float re[4], im[4];
        #pragma unroll
        for (int j = 0; j < 4; j++) {
            re[j] = v0 + (((ky0+j) & 1) ? -v64 : v64);
            im[j] = 0.f;
        }
        #pragma unroll 7
        for (int w = 1; w < 64; w++) {
            float a = vr[w], b = vr[128-w];
            float s_ = a + b, d_ = a - b;
            float4 c4 = *(const float4*)(Tc + w*16 + ky0);
            float4 s4 = *(const float4*)(Ts + w*16 + ky0);
            re[0] += s_*c4.x; im[0] -= d_*s4.x;
            re[1] += s_*c4.y; im[1] -= d_*s4.y;
            re[2] += s_*c4.z; im[2] -= d_*s4.z;
            re[3] += s_*c4.w; im[3] -= d_*s4.w;
        }
        #pragma unroll
        for (int j = 0; j < 4; j++)
            Az[(half*64 + hl)*16 + ky0 + j] = make_float2(re[j], im[j]);
    }
    __syncthreads();
    int g = tid >> 4, ky = tid & 15;
    if (g == 0) {
        float rex=0.f, imx=0.f, re16=0.f, im16=0.f;
        int t = 0;
        for (int h = 0; h < 128; h++) {
            float2 a = Az[h*16 + ky];
            rex += a.x; imx += a.y;
            float cc = ct[t], ss = st[t];
            re16 += a.x*cc - a.y*ss;
            im16 += a.y*cc + a.x*ss;
            t = (t + 16) & 127;
        }
        g_X[((bb*32 + 0 )*16 + ky)*32 + c] = make_float2(rex,  imx);
        g_X[((bb*32 + 16)*16 + ky)*32 + c] = make_float2(re16, im16);
    } else {
        float u=0.f, v=0.f, pp=0.f, qq=0.f;
        int t = 0;
        for (int h = 0; h < 128; h++) {
            float2 a = Az[h*16 + ky];
            float cc = ct[t], ss = st[t];
            u  += a.x*cc; qq += a.x*ss;
            pp += a.y*cc; v  += a.y*ss;
            t = (t + g) & 127;
        }
        g_X[((bb*32 + g     )*16 + ky)*32 + c] = make_float2(u+v, pp-qq);
        g_X[((bb*32 + (32-g))*16 + ky)*32 + c] = make_float2(u-v, pp+qq);
    }
}

// spectral mix (per-sample)
__global__ __launch_bounds__(256) void k_mix(const float* __restrict__ wr,
                                             const float* __restrict__ wi, int l) {
    __shared__ float2 Xs[16*32];
    int bb = blockIdx.x >> 5, kxi = blockIdx.x & 31;
    int e = g_idx[bb];
    int r   = (kxi < 16) ? 0 : 1;
    int kxp = (kxi < 16) ? kxi : kxi - 16;
    const float2* src = g_X + ((bb*32 + kxi)*16)*32;
    for (int p = threadIdx.x; p < 512; p += 256) Xs[p] = src[p];
    __syncthreads();
    int base = ((e*4 + l)*2 + r)*(32*32*256);
    const float* wrb = wr + base + kxp*16;
    const float* wib = wi + base + kxp*16;
    for (int p = threadIdx.x; p < 512; p += 256) {
        int o = p >> 4, ky = p & 15;
        float re = 0.f, im = 0.f;
        #pragma unroll 8
        for (int i = 0; i < 32; i++) {
            float2 xv = Xs[ky*32 + i];
            float wre = wrb[i*8192 + o*256 + ky];
            float wim = wib[i*8192 + o*256 + ky];
            re += xv.x*wre - xv.y*wim;
            im += xv.x*wim + xv.y*wre;
        }
        g_Y[((bb*32 + o)*32 + kxi)*16 + ky] = make_float2(re, im);
    }
}

// inverse h-DFT with S/D symmetry
__global__ __launch_bounds__(256) void k_idft2() {
    __shared__ __align__(16) float2 Ssm[17*16];
    __shared__ __align__(16) float2 Dsm[17*16];
    __shared__ float ct[128], st[128];
    int bb = blockIdx.x >> 5, o = blockIdx.x & 31;
    int tid = threadIdx.x;
    if (tid < 128) {
        float ang = 6.283185307179586f*(float)tid/128.0f;
        ct[tid] = cosf(ang); st[tid] = sinf(ang);
    }
    const float2* Yb = g_Y + ((bb*32 + o)*32)*16;
    for (int p = tid; p < 272; p += 256) {
        int g = p >> 4, ky = p & 15;
        float2 S, D;
        if (g == 0)      { S = Yb[ky]; D = make_float2(0.f, 0.f); }
        else if (g < 16) {
            float2 a = Yb[g*16 + ky], b = Yb[(32-g)*16 + ky];
            S = make_float2(a.x+b.x, a.y+b.y);
            D = make_float2(a.x-b.x, a.y-b.y);
        } else {
            float2 a = Yb[16*16 + ky];
            S = a; D = make_float2(-a.x, -a.y);
        }
        Ssm[p] = S; Dsm[p] = D;
    }
    __syncthreads();
    int h = tid >> 1, ky0 = (tid & 1)*8;
    float zr[8], zi[8];
    #pragma unroll
    for (int j = 0; j < 8; j++) { zr[j]=0.f; zi[j]=0.f; }
    #pragma unroll
    for (int g = 0; g <= 16; g++) {
        int t = (g*h) & 127;
        float cc = ct[t], ss = st[t];
        const float4* Sp = (const float4*)(Ssm + g*16 + ky0);
        const float4* Dp = (const float4*)(Dsm + g*16 + ky0);
        #pragma unroll
        for (int jj = 0; jj < 4; jj++) {
            float4 Sv = Sp[jj], Dv = Dp[jj];
            zr[jj*2]   += cc*Sv.x - ss*Dv.y;
            zi[jj*2]   += cc*Sv.y + ss*Dv.x;
            zr[jj*2+1] += cc*Sv.z - ss*Dv.w;
            zi[jj*2+1] += cc*Sv.w + ss*Dv.z;
        }
    }
    float2* dst = g_Z + ((bb*32 + o)*128 + h)*16 + ky0;
    #pragma unroll
    for (int j = 0; j < 8; j++) dst[j] = make_float2(zr[j], zi[j]);
}

// ===== combine with w-mirror split: skip GEMM (K=33) + spec GEMM (K=31, half w) =====
// spec[o][w] uses cos-even/sin-odd symmetry: out[w]=SK+C+S, out[128-w]=SK'+C-S.
// dyn smem layout (floats): Tc[16*68] @0, Ts[16*68] @1088, Vv[33*128] @2176,
//                           SK[32*128] @6400, Acos[16*32] @10496, Asin[16*32] @11008,
//                           Askip[33*32] @11520  -> total 12576 floats (50304 B)
__global__ __launch_bounds__(256) void k_comb2(const float* __restrict__ sw,
                                               const float* __restrict__ sb,
                                               int l, int last) {
    extern __shared__ float cm[];
    float* Tc    = cm;
    float* Ts    = cm + 1088;
    float* Vv    = cm + 2176;
    float* SK    = cm + 6400;
    float* Acos_ = cm + 10496;
    float* Asin_ = cm + 11008;
    float* Askip = cm + 11520;
    int bb = blockIdx.x >> 7, h = blockIdx.x & 127;
    int e = g_idx[bb];
    int tid = threadIdx.x;

    // twiddle tables, w 0..64 (pad to 68)
    for (int p = tid; p < 1088; p += 256) {
        int k = p/68, w = p - k*68;
        Tc[p] = (w < 65) ? g_Tw[k*128 + w] : 0.f;
        Ts[p] = (k >= 1 && w < 65) ? g_Tw[(15+k)*128 + w] : 0.f;
    }
    // Vv rows 0..31: v channels; row 32: ones
    for (int p = tid; p < 1024; p += 256) {
        int i = p >> 5, q = p & 31;
        ((float4*)(Vv + i*128))[q] = ((const float4*)(g_v + ((bb*32+i)*128+h)*128))[q];
    }
    if (tid < 128) Vv[32*128 + tid] = 1.0f;
    // A factors from Z
    for (int p = tid; p < 512; p += 256) {
        int o = p >> 4, ky = p & 15;
        float2 z = g_Z[((bb*32+o)*128+h)*16 + ky];
        const float s2 = 2.0f/16384.0f;
        if (ky == 0) { Acos_[o] = z.x*(1.0f/16384.0f); Asin_[o] = 0.f; }
        else { Acos_[ky*32+o] = z.x*s2; Asin_[ky*32+o] = -z.y*s2; }
    }
    // skip weights + bias
    for (int p = tid; p < 1024; p += 256)
        Askip[(p>>5)*32 + (p & 31)] = sw[(e*4+l)*1024 + p];
    if (tid < 32) Askip[32*32 + tid] = sb[(e*4+l)*32 + tid];
    __syncthreads();

    // phase 1: skip GEMM K=33 -> SK[32][128]
    {
        int wg = tid & 31, og = tid >> 5;
        float acc[4][4];
        #pragma unroll
        for (int i = 0; i < 4; i++)
            #pragma unroll
            for (int j = 0; j < 4; j++) acc[i][j] = 0.f;
        #pragma unroll 3
        for (int k = 0; k < 33; k++) {
            float4 bv = ((const float4*)(Vv + k*128))[wg];
            float4 av = ((const float4*)(Askip + k*32))[og];
            acc[0][0]+=av.x*bv.x; acc[0][1]+=av.x*bv.y; acc[0][2]+=av.x*bv.z; acc[0][3]+=av.x*bv.w;
            acc[1][0]+=av.y*bv.x; acc[1][1]+=av.y*bv.y; acc[1][2]+=av.y*bv.z; acc[1][3]+=av.y*bv.w;
            acc[2][0]+=av.z*bv.x; acc[2][1]+=av.z*bv.y; acc[2][2]+=av.z*bv.z; acc[2][3]+=av.z*bv.w;
            acc[3][0]+=av.w*bv.x; acc[3][1]+=av.w*bv.y; acc[3][2]+=av.w*bv.z; acc[3][3]+=av.w*bv.w;
        }
        #pragma unroll
        for (int i = 0; i < 4; i++)
            ((float4*)(SK + (og*4+i)*128))[wg] = make_float4(acc[i][0], acc[i][1], acc[i][2], acc[i][3]);
    }
    __syncthreads();

    // phase 2: spec GEMM K=31 over w 0..63 with mirror
    {
        int wg = tid & 15, og = tid >> 4;    // w0 = wg*4 (0..63), o0 = og*2
        int w0 = wg*4, o0 = og*2;
        float C[2][4], S[2][4];
        #pragma unroll
        for (int oo = 0; oo < 2; oo++)
            #pragma unroll
            for (int j = 0; j < 4; j++) { C[oo][j] = 0.f; S[oo][j] = 0.f; }
        #pragma unroll 4
        for (int k = 0; k < 16; k++) {
            float4 bv = *(const float4*)(Tc + k*68 + w0);
            float a0 = Acos_[k*32 + o0], a1 = Acos_[k*32 + o0 + 1];
            C[0][0]+=a0*bv.x; C[0][1]+=a0*bv.y; C[0][2]+=a0*bv.z; C[0][3]+=a0*bv.w;
            C[1][0]+=a1*bv.x; C[1][1]+=a1*bv.y; C[1][2]+=a1*bv.z; C[1][3]+=a1*bv.w;
        }
        #pragma unroll 5
        for (int k = 1; k < 16; k++) {
            float4 bv = *(const float4*)(Ts + k*68 + w0);
            float a0 = Asin_[k*32 + o0], a1 = Asin_[k*32 + o0 + 1];
            S[0][0]+=a0*bv.x; S[0][1]+=a0*bv.y; S[0][2]+=a0*bv.z; S[0][3]+=a0*bv.w;
            S[1][0]+=a1*bv.x; S[1][1]+=a1*bv.y; S[1][2]+=a1*bv.z; S[1][3]+=a1*bv.w;
        }
        #pragma unroll
        for (int oo = 0; oo < 2; oo++) {
            int o = o0 + oo;
            float* grow = g_v + ((bb*32+o)*128+h)*128;
            const float* skr = SK + o*128;
            // left: w0..w0+3 (contiguous)
            float lv[4];
            #pragma unroll
            for (int j = 0; j < 4; j++) {
                float v = skr[w0+j] + C[oo][j] + S[oo][j];
                lv[j] = last ? v : gelu_tanh(v);
            }
            *(float4*)(grow + w0) = make_float4(lv[0], lv[1], lv[2], lv[3]);
            // right (mirror): 128-(w0+j), skip w==0
            #pragma unroll
            for (int j = 0; j < 4; j++) {
                int w = w0 + j;
                if (w == 0) continue;
                float v = skr[128-w] + C[oo][j] - S[oo][j];
                grow[128-w] = last ? v : gelu_tanh(v);
            }
        }
    }
    // w = 64: cos(64k*2pi/128) = (-1)^k, sin = 0
    if (tid < 32) {
        int o = tid;
        float acc = SK[o*128 + 64];
        #pragma unroll
        for (int k = 0; k < 16; k++)
            acc += (k & 1) ? -Acos_[k*32 + o] : Acos_[k*32 + o];
        if (!last) acc = gelu_tanh(acc);
        g_v[((bb*32+o)*128+h)*128 + 64] = acc;
    }
}

// projection
__global__ __launch_bounds__(256, 2) void k_proj2(
        const float* __restrict__ p1w, const float* __restrict__ p1b,
        const float* __restrict__ p2w, const float* __restrict__ p2b,
        float* __restrict__ out) {
    __shared__ float vs [32*128];
    __shared__ float w1p[32*128];
    __shared__ float red[16*128];
    __shared__ float b1s[128], p2s[128];
    int bb = blockIdx.x >> 7, h = blockIdx.x & 127;
    int e = g_idx[bb];
    int tid = threadIdx.x;
    #pragma unroll
    for (int j = 0; j < 4; j++) {
        int p = tid + 256*j;
        int i = p >> 5, q = p & 31;
        ((float4*)(vs + i*128))[q] = ((const float4*)(g_v + ((bb*32+i)*128+h)*128))[q];
    }
    for (int p = tid; p < 4096; p += 256) {
        float val = p1w[e*4096 + p];
        int c = p >> 7, pch = p & 127;
        w1p[c*128 + (pch & 15)*8 + (pch >> 4)] = val;
    }
    if (tid < 128) {
        b1s[tid] = p1b[e*128 + tid];
        p2s[tid] = p2w[e*128 + tid];
    }
    __syncthreads();

    int wg = tid & 15, pg = tid >> 4;
    int w0 = wg*8;
    float acc[8][8];
    #pragma unroll
    for (int i = 0; i < 8; i++)
        #pragma unroll
        for (int j = 0; j < 8; j++) acc[i][j] = 0.f;
    #pragma unroll 2
    for (int c = 0; c < 32; c++) {
        float4 v0 = ((const float4*)(vs + c*128 + w0))[0];
        float4 v1 = ((const float4*)(vs + c*128 + w0))[1];
        float4 u0 = ((const float4*)(w1p + c*128 + pg*8))[0];
        float4 u1 = ((const float4*)(w1p + c*128 + pg*8))[1];
        float vv[8] = {v0.x,v0.y,v0.z,v0.w,v1.x,v1.y,v1.z,v1.w};
        float uu[8] = {u0.x,u0.y,u0.z,u0.w,u1.x,u1.y,u1.z,u1.w};
        #pragma unroll
        for (int i = 0; i < 8; i++)
            #pragma unroll
            for (int j = 0; j < 8; j++)
                acc[i][j] += uu[i]*vv[j];
    }
    float part[8];
    #pragma unroll
    for (int j = 0; j < 8; j++) part[j] = 0.f;
    #pragma unroll
    for (int i = 0; i < 8; i++) {
        int pch = pg + 16*i;
        float bias = b1s[pch], p2v = p2s[pch];
        #pragma unroll
        for (int j = 0; j < 8; j++)
            part[j] += gelu_tanh(acc[i][j] + bias)*p2v;
    }
    #pragma unroll
    for (int j = 0; j < 8; j++) red[pg*128 + w0 + j] = part[j];
    __syncthreads();
    if (tid < 128) {
        int w = tid;
        float o = p2b[e];
        #pragma unroll
        for (int pg2 = 0; pg2 < 16; pg2++) o += red[pg2*128 + w];
        out[bb*16384 + h*128 + w] = o;
    }
}

// ========================= launch =========================
extern "C" void kernel_launch(void* const* d_in, const int* in_sizes, int n_in,
                              void* d_out, int out_size) {
    const float* x        = (const float*)d_in[0];
    const float* enc_in_w = (const float*)d_in[1];
    const float* enc_in_b = (const float*)d_in[2];
    const float* qkv_w    = (const float*)d_in[3];
    const float* qkv_b    = (const float*)d_in[4];
    const float* ao_w     = (const float*)d_in[5];
    const float* ao_b     = (const float*)d_in[6];
    const float* ln1_s    = (const float*)d_in[7];
    const float* ln1_b    = (const float*)d_in[8];
    const float* ff1_w    = (const float*)d_in[9];
    const float* ff1_b    = (const float*)d_in[10];
    const float* ff2_w    = (const float*)d_in[11];
    const float* ff2_b    = (const float*)d_in[12];
    const float* ln2_s    = (const float*)d_in[13];
    const float* ln2_b    = (const float*)d_in[14];
    const float* fc_w     = (const float*)d_in[15];
    const float* fc_b     = (const float*)d_in[16];
    const float* lift_w   = (const float*)d_in[17];
    const float* lift_b   = (const float*)d_in[18];
    const float* spec_wr  = (const float*)d_in[19];
    const float* spec_wi  = (const float*)d_in[20];
    const float* skip_w   = (const float*)d_in[21];
    const float* skip_b   = (const float*)d_in[22];
    const float* p1_w     = (const float*)d_in[23];
    const float* p1_b     = (const float*)d_in[24];
    const float* p2_w     = (const float*)d_in[25];
    const float* p2_b     = (const float*)d_in[26];

    cudaFuncSetAttribute(k_dft2,  cudaFuncAttributeMaxDynamicSharedMemorySize, 59392);
    cudaFuncSetAttribute(k_fxy,   cudaFuncAttributeMaxDynamicSharedMemorySize, 59392);
    cudaFuncSetAttribute(k_comb2, cudaFuncAttributeMaxDynamicSharedMemorySize, 50304);

    // twiddle table + input 2D DFT (independent of router)
    k_tw<<<32, 128>>>();
    k_fxy<<<Bn, 256, 59392>>>(x);

    // ---- router ----
    k_encode<<<256, 256>>>(x, enc_in_w, enc_in_b);
    for (int l = 0; l < NENCn; l++) {
        k_attn_qkv<<<Bn*NHn, 256>>>(qkv_w, qkv_b, l);
        k_plf<<<(Bn*Sn)/16, 256>>>(ao_w, ao_b, ln1_s, ln1_b,
                                   ff1_w, ff1_b, ff2_w, ff2_b, ln2_s, ln2_b, l);
    }
    k_head<<<Bn, 128>>>(fc_w, fc_b);

    // ---- FNO ----
    k_lift<<<Bn*Hn, 256>>>(x, lift_w, lift_b);
    k_x0<<<Bn, 256>>>(lift_w, lift_b);
    for (int l = 0; l < NLn; l++) {
        if (l > 0) k_dft2<<<Bn*CHn, 256, 59392>>>();
        k_mix<<<Bn*KXn, 256>>>(spec_wr, spec_wi, l);
        k_idft2<<<Bn*CHn, 256>>>();
        k_comb2<<<Bn*Hn, 256, 50304>>>(skip_w, skip_b, l, (l == NLn-1) ? 1 : 0);
    }
    k_proj2<<<Bn*Hn, 256>>>(p1_w, p1_b, p2_w, p2_b, (float*)d_out);
}

// round 16
// speedup vs baseline: 1.0509x; 1.0509x over previous
#include <cuda_runtime.h>
#include <cstdint>
#include <math.h>

// ---------------- problem constants ----------------
#define Bn   32
#define Sn   128
#define HDn  64
#define NHn  4
#define NENCn 2
#define En   8
#define NLn  4
#define CHn  32
#define Hn   128
#define Wn   128
#define PCHn 128
#define KXn  32

// ---------------- device scratch ----------------
__device__ float  g_h  [Bn*Sn*HDn];
__device__ float  g_att[Bn*Sn*HDn];
__device__ int    g_idx[Bn];
__device__ float  g_v[Bn*CHn*Hn*Wn];          // 64 MB activation
__device__ float2 g_FXY[Bn*KXn*16];           // 2D partial DFT of x [b][kx][ky]
__device__ float2 g_X[Bn*KXn*16*CHn];         // fwd coeffs [b][kx][ky][c]
__device__ float2 g_Y[Bn*CHn*KXn*16];         // mixed [b][o][kx][ky]
__device__ float2 g_Z[Bn*CHn*Hn*16];          // inv h-DFT [b][o][h][ky]
__device__ float  g_Tw[32*128];               // irfft-w twiddles (31 rows) + ones row

__device__ __forceinline__ float gelu_tanh(float x) {
    float x3 = x*x*x;
    float z  = 0.7978845608028654f*(x + 0.044715f*x3);
    float t  = 1.0f - 2.0f/(__expf(2.0f*z) + 1.0f);
    return 0.5f*x*(1.0f + t);
}

// ========================= fused prologue =========================
// blocks 0..31: 2D partial DFT of input x (k_fxy body)
// block  32   : twiddle table init
// blocks 33..127: encode h = x_row0 * enc_w + enc_b (grid-stride)
__global__ __launch_bounds__(256) void k_pro(const float* __restrict__ x,
                                             const float* __restrict__ ew,
                                             const float* __restrict__ eb) {
    int tid = threadIdx.x;
    if (blockIdx.x >= 32) {
        if (blockIdx.x == 32) {
            for (int p = tid; p < 4096; p += 256) {
                int k = p >> 7, w = p & 127;
                float val;
                if (k == 0)       val = 1.0f;
                else if (k < 16)  { int t = (k*w) & 127;      val = cosf(0.0490873852123405f*(float)t); }
                else if (k < 31)  { int t = ((k-15)*w) & 127; val = sinf(0.0490873852123405f*(float)t); }
                else              val = 1.0f;
                g_Tw[p] = val;
            }
        } else {
            const int tot = Bn*Sn*HDn;
            int i = (blockIdx.x - 33)*256 + tid;
            for (; i < tot; i += 95*256) {
                int d = i & 63;
                int s = (i >> 6) & 127;
                int bb = i >> 13;
                g_h[i] = x[bb*(Hn*Wn) + s]*ew[d] + eb[d];
            }
        }
        return;
    }
    // ---- fxy body ----
    extern __shared__ float sm[];
    float*  vs = sm;
    float2* Az = (float2*)(sm + 8448);
    float*  Tc = sm + 8448 + 4096;
    float*  Ts = Tc + 1024;
    float*  ct = Ts + 1024;
    float*  st = ct + 128;
    int bb = blockIdx.x;
    if (tid < 128) {
        float ang = 6.283185307179586f*(float)tid/128.0f;
        ct[tid] = cosf(ang); st[tid] = sinf(ang);
    }
    for (int p = tid; p < 1024; p += 256) {
        int w = p >> 4, k = p & 15;
        int t = (w*k) & 127;
        float ang = 0.0490873852123405f*(float)t;
        Tc[p] = cosf(ang); Ts[p] = sinf(ang);
    }
    const float* vg = x + bb*16384;
    int hl = tid >> 2, kq = tid & 3, ky0 = kq*4;
    for (int half = 0; half < 2; half++) {
        __syncthreads();
        for (int p = tid; p < 2048; p += 256) {
            int r = p >> 5, q = p & 31;
            ((float4*)(vs + r*132))[q] = ((const float4*)(vg + (half*64 + r)*128))[q];
        }
        __syncthreads();
        const float* vr = vs + hl*132;
        float v0 = vr[0], v64 = vr[64];
        float re[4], im[4];
        #pragma unroll
        for (int j = 0; j < 4; j++) {
            re[j] = v0 + (((ky0+j) & 1) ? -v64 : v64);
            im[j] = 0.f;
        }
        #pragma unroll 7
        for (int w = 1; w < 64; w++) {
            float a = vr[w], b = vr[128-w];
            float s_ = a + b, d_ = a - b;
            float4 c4 = *(const float4*)(Tc + w*16 + ky0);
            float4 s4 = *(const float4*)(Ts + w*16 + ky0);
            re[0] += s_*c4.x; im[0] -= d_*s4.x;
            re[1] += s_*c4.y; im[1] -= d_*s4.y;
            re[2] += s_*c4.z; im[2] -= d_*s4.z;
            re[3] += s_*c4.w; im[3] -= d_*s4.w;
        }
        #pragma unroll
        for (int j = 0; j < 4; j++)
            Az[(half*64 + hl)*16 + ky0 + j] = make_float2(re[j], im[j]);
    }
    __syncthreads();
    int g = tid >> 4, ky = tid & 15;
    if (g == 0) {
        float rex=0.f, imx=0.f, re16=0.f, im16=0.f;
        int t = 0;
        for (int h = 0; h < 128; h++) {
            float2 a = Az[h*16 + ky];
            rex += a.x; imx += a.y;
            float cc = ct[t], ss = st[t];
            re16 += a.x*cc - a.y*ss;
            im16 += a.y*cc + a.x*ss;
            t = (t + 16) & 127;
        }
        g_FXY[(bb*32 + 0 )*16 + ky] = make_float2(rex,  imx);
        g_FXY[(bb*32 + 16)*16 + ky] = make_float2(re16, im16);
    } else {
        float u=0.f, v=0.f, pp=0.f, qq=0.f;
        int t = 0;
        for (int h = 0; h < 128; h++) {
            float2 a = Az[h*16 + ky];
            float cc = ct[t], ss = st[t];
            u  += a.x*cc; qq += a.x*ss;
            pp += a.y*cc; v  += a.y*ss;
            t = (t + g) & 127;
        }
        g_FXY[(bb*32 + g     )*16 + ky] = make_float2(u+v, pp-qq);
        g_FXY[(bb*32 + (32-g))*16 + ky] = make_float2(u-v, pp+qq);
    }
}

// ========================= ROUTER =========================

// fused qkv + flash attention, 2-way split softmax; block = (b, head), 256 threads
__global__ __launch_bounds__(256) void k_attn_qkv(const float* __restrict__ qw,
                                                  const float* __restrict__ qb, int l) {
    __shared__ float buf[11264];
    int b = blockIdx.x >> 2, hd = blockIdx.x & 3;
    int tid = threadIdx.x;
    int i = tid & 127, half = tid >> 7;

    float* hs = buf;
    float* Ws = buf + 8192;
    for (int p = tid; p < 2048; p += 256)
        ((float4*)hs)[p] = ((const float4*)(g_h + b*8192))[p];
    {
        const float* W = qw + l*64*192;
        for (int p = tid; p < 3072; p += 256) {
            int d = p/48, c = p - d*48;
            int gc = hd*16 + (c & 15) + (c >> 4)*64;
            Ws[p] = W[d*192 + gc];
        }
    }
    __syncthreads();

    float q[16], kv[16];
    {
        const float* qbl = qb + l*192 + hd*16;
        int kvoff = half ? 128 : 64;
        #pragma unroll
        for (int j = 0; j < 16; j++) { q[j] = qbl[j]; kv[j] = qbl[kvoff + j]; }
        int woff = half ? 8 : 4;
        for (int d = 0; d < 64; d++) {
            float hv = hs[i*64 + d];
            const float4* wr = (const float4*)(Ws + d*48);
            #pragma unroll
            for (int jj = 0; jj < 4; jj++) {
                float4 wq = wr[jj], wk = wr[woff + jj];
                q [jj*4+0] += hv*wq.x; q [jj*4+1] += hv*wq.y; q [jj*4+2] += hv*wq.z; q [jj*4+3] += hv*wq.w;
                kv[jj*4+0] += hv*wk.x; kv[jj*4+1] += hv*wk.y; kv[jj*4+2] += hv*wk.z; kv[jj*4+3] += hv*wk.w;
            }
        }
    }
    __syncthreads();

    float* ks   = buf;
    float* vs   = buf + 2048;
    float* mArr = buf + 4096;
    float* sArr = buf + 4352;
    float* oArr = buf + 4608;
    {
        float* dst = (half ? vs : ks) + i*16;
        #pragma unroll
        for (int j = 0; j < 16; j++) dst[j] = kv[j];
    }
    __syncthreads();

    int j0 = half*64;
    float m = -1e30f, ssum = 0.f;
    float out[16];
    #pragma unroll
    for (int d = 0; d < 16; d++) out[d] = 0.f;
    for (int jj = 0; jj < 64; jj += 4) {
        float s[4];
        #pragma unroll
        for (int r = 0; r < 4; r++) {
            const float4* kr = (const float4*)(ks + (j0 + jj + r)*16);
            float4 a0 = kr[0], a1 = kr[1], a2 = kr[2], a3 = kr[3];
            float p0 = q[0]*a0.x  + q[1]*a0.y  + q[2]*a0.z  + q[3]*a0.w;
            float p1 = q[4]*a1.x  + q[5]*a1.y  + q[6]*a1.z  + q[7]*a1.w;
            float p2 = q[8]*a2.x  + q[9]*a2.y  + q[10]*a2.z + q[11]*a2.w;
            float p3 = q[12]*a3.x + q[13]*a3.y + q[14]*a3.z + q[15]*a3.w;
            s[r] = ((p0 + p1) + (p2 + p3))*0.25f;
        }
        float mn = fmaxf(m, fmaxf(fmaxf(s[0], s[1]), fmaxf(s[2], s[3])));
        float corr = __expf(m - mn);
        float w0 = __expf(s[0] - mn), w1 = __expf(s[1] - mn);
        float w2 = __expf(s[2] - mn), w3 = __expf(s[3] - mn);
        ssum = ssum*corr + ((w0 + w1) + (w2 + w3));
        #pragma unroll
        for (int d = 0; d < 16; d++) out[d] *= corr;
        {
            const float4* v0 = (const float4*)(vs + (j0 + jj    )*16);
            const float4* v1 = (const float4*)(vs + (j0 + jj + 1)*16);
            const float4* v2 = (const float4*)(vs + (j0 + jj + 2)*16);
            const float4* v3 = (const float4*)(vs + (j0 + jj + 3)*16);
            #pragma unroll
            for (int g4 = 0; g4 < 4; g4++) {
                float4 b0 = v0[g4], b1 = v1[g4], b2 = v2[g4], b3 = v3[g4];
                out[g4*4+0] += w0*b0.x + w1*b1.x + w2*b2.x + w3*b3.x;
                out[g4*4+1] += w0*b0.y + w1*b1.y + w2*b2.y + w3*b3.y;
                out[g4*4+2] += w0*b0.z + w1*b1.z + w2*b2.z + w3*b3.z;
                out[g4*4+3] += w0*b0.w + w1*b1.w + w2*b2.w + w3*b3.w;
            }
        }
        m = mn;
    }
    mArr[tid] = m; sArr[tid] = ssum;
    {
        float* od = oArr + tid*16;
        #pragma unroll
        for (int d = 0; d < 16; d++) od[d] = out[d];
    }
    __syncthreads();

    if (half == 0) {
        float m1 = mArr[128 + i], s1v = sArr[128 + i];
        float M  = fmaxf(m, m1);
        float c0 = __expf(m - M), c1 = __expf(m1 - M);
        float inv = 1.0f/(ssum*c0 + s1v*c1);
        const float* o1 = oArr + (128 + i)*16;
        float* ob = g_att + (b*128 + i)*64 + hd*16;
        #pragma unroll
        for (int d = 0; d < 16; d++) ob[d] = (out[d]*c0 + o1[d]*c1)*inv;
    }
}

// fused: h = LN1(h + att@ao + ab); h = LN2(h + relu(h@W1+b1)@W2 + b2)
__global__ __launch_bounds__(256) void k_plf(
        const float* __restrict__ aw, const float* __restrict__ ab,
        const float* __restrict__ lns, const float* __restrict__ lnb,
        const float* __restrict__ w1, const float* __restrict__ b1,
        const float* __restrict__ w2, const float* __restrict__ b2,
        const float* __restrict__ ln2s, const float* __restrict__ ln2b, int l) {
    __shared__ float as_[1024], ts[1024], hs[1024];
    __shared__ float hid[4096];
    __shared__ float red[4096];
    int row0 = blockIdx.x*16;
    int tid = threadIdx.x;
    int warp = tid >> 5, lane = tid & 31;

    for (int p = tid; p < 1024; p += 256) as_[p] = g_att[row0*64 + p];
    __syncthreads();
    {
        const float* wl = aw + l*4096;
        int dq = tid & 15, rq = (tid >> 4) & 3, js = tid >> 6;
        int d0 = dq*4, r0 = rq*4, e0 = js*16;
        float acc[4][4];
        #pragma unroll
        for (int rr = 0; rr < 4; rr++)
            #pragma unroll
            for (int dd = 0; dd < 4; dd++) acc[rr][dd] = 0.f;
        #pragma unroll 4
        for (int ee = 0; ee < 16; ee++) {
            int eidx = e0 + ee;
            float4 wv = *(const float4*)(wl + eidx*64 + d0);
            #pragma unroll
            for (int rr = 0; rr < 4; rr++) {
                float hv = as_[(r0+rr)*64 + eidx];
                acc[rr][0] += hv*wv.x; acc[rr][1] += hv*wv.y;
                acc[rr][2] += hv*wv.z; acc[rr][3] += hv*wv.w;
            }
        }
        #pragma unroll
        for (int rr = 0; rr < 4; rr++)
            #pragma unroll
            for (int dd = 0; dd < 4; dd++)
                red[js*1024 + (r0+rr)*64 + d0+dd] = acc[rr][dd];
    }
    __syncthreads();
    for (int p = tid; p < 1024; p += 256) {
        int r = p >> 6, d = p & 63;
        ts[p] = red[p] + red[1024+p] + red[2048+p] + red[3072+p]
              + g_h[(row0+r)*64 + d] + ab[l*64 + d];
    }
    __syncthreads();
    {
        const float* s_ = lns + l*64; const float* b_ = lnb + l*64;
        #pragma unroll
        for (int rr = 0; rr < 2; rr++) {
            int r = warp*2 + rr;
            float a = ts[r*64+lane], bv = ts[r*64+32+lane];
            float s = a + bv, qq = a*a + bv*bv;
            #pragma unroll
            for (int off = 16; off > 0; off >>= 1) {
                s  += __shfl_xor_sync(0xffffffff, s,  off);
                qq += __shfl_xor_sync(0xffffffff, qq, off);
            }
            float mu = s*(1.0f/64.0f);
            float var = qq*(1.0f/64.0f) - mu*mu;
            float rs = rsqrtf(var + 1e-5f);
            hs[r*64+lane]    = (a  - mu)*rs*s_[lane]    + b_[lane];
            hs[r*64+32+lane] = (bv - mu)*rs*s_[32+lane] + b_[32+lane];
        }
    }
    __syncthreads();
    {
        const float* W1 = w1 + l*16384;
        int rq = tid >> 6, jg = tid & 63;
        int j0 = jg*4;
        float4 bv = *(const float4*)(b1 + l*256 + j0);
        float acc[4][4];
        #pragma unroll
        for (int rr = 0; rr < 4; rr++) {
            acc[rr][0]=bv.x; acc[rr][1]=bv.y; acc[rr][2]=bv.z; acc[rr][3]=bv.w;
        }
        #pragma unroll 4
        for (int d = 0; d < 64; d++) {
            float4 wv = *(const float4*)(W1 + d*256 + j0);
            #pragma unroll
            for (int rr = 0; rr < 4; rr++) {
                float hv = hs[(rq*4+rr)*64 + d];
                acc[rr][0] += hv*wv.x; acc[rr][1] += hv*wv.y;
                acc[rr][2] += hv*wv.z; acc[rr][3] += hv*wv.w;
            }
        }
        #pragma unroll
        for (int rr = 0; rr < 4; rr++)
            #pragma unroll
            for (int jj = 0; jj < 4; jj++)
                hid[(rq*4+rr)*256 + j0 + jj] = fmaxf(acc[rr][jj], 0.0f);
    }
    __syncthreads();
    {
        const float* W2 = w2 + l*16384;
        int dq = tid & 15, rq = (tid >> 4) & 3, js = tid >> 6;
        int d0 = dq*4, r0 = rq*4, j0 = js*64;
        float acc[4][4];
        #pragma unroll
        for (int rr = 0; rr < 4; rr++)
            #pragma unroll
            for (int dd = 0; dd < 4; dd++) acc[rr][dd] = 0.f;
        #pragma unroll 4
        for (int jj = 0; jj < 64; jj++) {
            int j = j0 + jj;
            float4 wv = *(const float4*)(W2 + j*64 + d0);
            #pragma unroll
            for (int rr = 0; rr < 4; rr++) {
                float hv = hid[(r0+rr)*256 + j];
                acc[rr][0] += hv*wv.x; acc[rr][1] += hv*wv.y;
                acc[rr][2] += hv*wv.z; acc[rr][3] += hv*wv.w;
            }
        }
        #pragma unroll
        for (int rr = 0; rr < 4; rr++)
            #pragma unroll
            for (int dd = 0; dd < 4; dd++)
                red[js*1024 + (r0+rr)*64 + d0+dd] = acc[rr][dd];
    }
    __syncthreads();
    for (int p = tid; p < 1024; p += 256) {
        int d = p & 63;
        ts[p] = red[p] + red[1024+p] + red[2048+p] + red[3072+p] + hs[p] + b2[l*64+d];
    }
    __syncthreads();
    {
        const float* s_ = ln2s + l*64; const float* b_ = ln2b + l*64;
        #pragma unroll
        for (int rr = 0; rr < 2; rr++) {
            int r = warp*2 + rr;
            float a = ts[r*64+lane], bv = ts[r*64+32+lane];
            float s = a + bv, qq = a*a + bv*bv;
            #pragma unroll
            for (int off = 16; off > 0; off >>= 1) {
                s  += __shfl_xor_sync(0xffffffff, s,  off);
                qq += __shfl_xor_sync(0xffffffff, qq, off);
            }
            float mu = s*(1.0f/64.0f);
            float var = qq*(1.0f/64.0f) - mu*mu;
            float rs = rsqrtf(var + 1e-5f);
            g_h[(row0+r)*64+lane]    = (a  - mu)*rs*s_[lane]    + b_[lane];
            g_h[(row0+r)*64+32+lane] = (bv - mu)*rs*s_[32+lane] + b_[32+lane];
        }
    }
}

__global__ __launch_bounds__(128) void k_head(const float* __restrict__ fcw,
                                              const float* __restrict__ fcb) {
    __shared__ float fe[128];
    int b = blockIdx.x;
    int t = threadIdx.x;
    int d = t & 63, sh = t >> 6;
    float acc = 0.f;
    for (int s = sh*64; s < sh*64 + 64; s++) acc += g_h[(b*128+s)*64 + d];
    fe[t] = acc;
    __syncthreads();
    if (t < 64) fe[t] = (fe[t] + fe[t+64])*(1.0f/128.0f);
    __syncthreads();
    if (t == 0) {
        float best = -1e30f; int bi = 0;
        for (int e = 0; e < En; e++) {
            float a = fcb[e];
            for (int dd = 0; dd < 64; dd++) a += fe[dd]*fcw[dd*En + e];
            if (a > best) { best = a; bi = e; }
        }
        g_idx[b] = bi;
    }
}

// ========================= FNO =========================

// fused lift (blocks 0..4095) + layer-0 X expansion (blocks 4096..4127)
__global__ __launch_bounds__(256) void k_liftx0(const float* __restrict__ x,
                                                const float* __restrict__ lw,
                                                const float* __restrict__ lb) {
    __shared__ float xr[128];
    __shared__ float ws[32], bs[32];
    __shared__ float2 fx[512];
    int tid = threadIdx.x;
    if (blockIdx.x < 4096) {
        int bb = blockIdx.x >> 7, h = blockIdx.x & 127;
        int e = g_idx[bb];
        if (tid < 128) xr[tid] = x[bb*16384 + h*128 + tid];
        if (tid < 32) { ws[tid] = lw[e*32+tid]; bs[tid] = lb[e*32+tid]; }
        __syncthreads();
        for (int p = tid; p < 4096; p += 256) {
            int d = p >> 7, w = p & 127;
            g_v[((bb*32+d)*128 + h)*128 + w] = xr[w]*ws[d] + bs[d];
        }
    } else {
        int bb = blockIdx.x - 4096;
        int e = g_idx[bb];
        if (tid < 32) { ws[tid] = lw[e*32+tid]; bs[tid] = lb[e*32+tid]; }
        for (int p = tid; p < 512; p += 256) fx[p] = g_FXY[bb*512 + p];
        __syncthreads();
        for (int p = tid; p < 16384; p += 256) {
            int c = p & 31, rest = p >> 5;
            float2 f = fx[rest];
            float2 o = make_float2(ws[c]*f.x, ws[c]*f.y);
            if (rest == 0) o.x += 16384.0f*bs[c];
            g_X[(bb*512 + rest)*32 + c] = o;
        }
    }
}

// fused 2D forward partial DFT per (b,c) — layers 1..3
__global__ __launch_bounds__(256) void k_dft2() {
    extern __shared__ float sm[];
    float*  vs = sm;
    float2* Az = (float2*)(sm + 8448);
    float*  Tc = sm + 8448 + 4096;
    float*  Ts = Tc + 1024;
    float*  ct = Ts + 1024;
    float*  st = ct + 128;
    int bb = blockIdx.x >> 5, c = blockIdx.x & 31;
    int tid = threadIdx.x;
    if (tid < 128) {
        float ang = 6.283185307179586f*(float)tid/128.0f;
        ct[tid] = cosf(ang); st[tid] = sinf(ang);
    }
    for (int p = tid; p < 1024; p += 256) {
        int w = p >> 4, k = p & 15;
        int t = (w*k) & 127;
        float ang = 0.0490873852123405f*(float)t;
        Tc[p] = cosf(ang); Ts[p] = sinf(ang);
    }
    const float* vg = g_v + (bb*32 + c)*16384;
    int hl = tid >> 2, kq = tid & 3, ky0 = kq*4;
    for (int half = 0; half < 2; half++) {
        __syncthreads();
        for (int p = tid; p < 2048; p += 256) {
            int r = p >> 5, q = p & 31;
            ((float4*)(vs + r*132))[q] = ((const float4*)(vg + (half*64 + r)*128))[q];
        }
        __syncthreads();
        const float* vr = vs + hl*132;
        float v0 = vr[0], v64 = vr[64];
        float re[4], im[4];
        #pragma unroll
        for (int j = 0; j < 4; j++) {
            re[j] = v0 + (((ky0+j) & 1) ? -v64 : v64);
            im[j] = 0.f;
        }
        #pragma unroll 7
        for (int w = 1; w < 64; w++) {
            float a = vr[w], b = vr[128-w];
            float s_ = a + b, d_ = a - b;
            float4 c4 = *(const float4*)(Tc + w*16 + ky0);
            float4 s4 = *(const float4*)(Ts + w*16 + ky0);
            re[0] += s_*c4.x; im[0] -= d_*s4.x;
            re[1] += s_*c4.y; im[1] -= d_*s4.y;
            re[2] += s_*c4.z; im[2] -= d_*s4.z;
            re[3] += s_*c4.w; im[3] -= d_*s4.w;
        }
        #pragma unroll
        for (int j = 0; j < 4; j++)
            Az[(half*64 + hl)*16 + ky0 + j] = make_float2(re[j], im[j]);
    }
    __syncthreads();
    int g = tid >> 4, ky = tid & 15;
    if (g == 0) {
        float rex=0.f, imx=0.f, re16=0.f, im16=0.f;
        int t = 0;
        for (int h = 0; h < 128; h++) {
            float2 a = Az[h*16 + ky];
            rex += a.x; imx += a.y;
            float cc = ct[t], ss = st[t];
            re16 += a.x*cc - a.y*ss;
            im16 += a.y*cc + a.x*ss;
            t = (t + 16) & 127;
        }
        g_X[((bb*32 + 0 )*16 + ky)*32 + c] = make_float2(rex,  imx);
        g_X[((bb*32 + 16)*16 + ky)*32 + c] = make_float2(re16, im16);
    } else {
        float u=0.f, v=0.f, pp=0.f, qq=0.f;
        int t = 0;
        for (int h = 0; h < 128; h++) {
            float2 a = Az[h*16 + ky];
            float cc = ct[t], ss = st[t];
            u  += a.x*cc; qq += a.x*ss;
            pp += a.y*cc; v  += a.y*ss;
            t = (t + g) & 127;
        }
        g_X[((bb*32 + g     )*16 + ky)*32 + c] = make_float2(u+v, pp-qq);
        g_X[((bb*32 + (32-g))*16 + ky)*32 + c] = make_float2(u-v, pp+qq);
    }
}

// spectral mix (per-sample)
__global__ __launch_bounds__(256) void k_mix(const float* __restrict__ wr,
                                             const float* __restrict__ wi, int l) {
    __shared__ float2 Xs[16*32];
    int bb = blockIdx.x >> 5, kxi = blockIdx.x & 31;
    int e = g_idx[bb];
    int r   = (kxi < 16) ? 0 : 1;
    int kxp = (kxi < 16) ? kxi : kxi - 16;
    const float2* src = g_X + ((bb*32 + kxi)*16)*32;
    for (int p = threadIdx.x; p < 512; p += 256) Xs[p] = src[p];
    __syncthreads();
    int base = ((e*4 + l)*2 + r)*(32*32*256);
    const float* wrb = wr + base + kxp*16;
    const float* wib = wi + base + kxp*16;
    for (int p = threadIdx.x; p < 512; p += 256) {
        int o = p >> 4, ky = p & 15;
        float re = 0.f, im = 0.f;
        #pragma unroll 8
        for (int i = 0; i < 32; i++) {
            float2 xv = Xs[ky*32 + i];
            float wre = wrb[i*8192 + o*256 + ky];
            float wim = wib[i*8192 + o*256 + ky];
            re += xv.x*wre - xv.y*wim;
            im += xv.x*wim + xv.y*wre;
        }
        g_Y[((bb*32 + o)*32 + kxi)*16 + ky] = make_float2(re, im);
    }
}

// inverse h-DFT with S/D symmetry
__global__ __launch_bounds__(256) void k_idft2() {
    __shared__ __align__(16) float2 Ssm[17*16];
    __shared__ __align__(16) float2 Dsm[17*16];
    __shared__ float ct[128], st[128];
    int bb = blockIdx.x >> 5, o = blockIdx.x & 31;
    int tid = threadIdx.x;
    if (tid < 128) {
        float ang = 6.283185307179586f*(float)tid/128.0f;
        ct[tid] = cosf(ang); st[tid] = sinf(ang);
    }
    const float2* Yb = g_Y + ((bb*32 + o)*32)*16;
    for (int p = tid; p < 272; p += 256) {
        int g = p >> 4, ky = p & 15;
        float2 S, D;
        if (g == 0)      { S = Yb[ky]; D = make_float2(0.f, 0.f); }
        else if (g < 16) {
            float2 a = Yb[g*16 + ky], b = Yb[(32-g)*16 + ky];
            S = make_float2(a.x+b.x, a.y+b.y);
            D = make_float2(a.x-b.x, a.y-b.y);
        } else {
            float2 a = Yb[16*16 + ky];
            S = a; D = make_float2(-a.x, -a.y);
        }
        Ssm[p] = S; Dsm[p] = D;
    }
    __syncthreads();
    int h = tid >> 1, ky0 = (tid & 1)*8;
    float zr[8], zi[8];
    #pragma unroll
    for (int j = 0; j < 8; j++) { zr[j]=0.f; zi[j]=0.f; }
    #pragma unroll
    for (int g = 0; g <= 16; g++) {
        int t = (g*h) & 127;
        float cc = ct[t], ss = st[t];
        const float4* Sp = (const float4*)(Ssm + g*16 + ky0);
        const float4* Dp = (const float4*)(Dsm + g*16 + ky0);
        #pragma unroll
        for (int jj = 0; jj < 4; jj++) {
            float4 Sv = Sp[jj], Dv = Dp[jj];
            zr[jj*2]   += cc*Sv.x - ss*Dv.y;
            zi[jj*2]   += cc*Sv.y + ss*Dv.x;
            zr[jj*2+1] += cc*Sv.z - ss*Dv.w;
            zi[jj*2+1] += cc*Sv.w + ss*Dv.z;
        }
    }
    float2* dst = g_Z + ((bb*32 + o)*128 + h)*16 + ky0;
    #pragma unroll
    for (int j = 0; j < 8; j++) dst[j] = make_float2(zr[j], zi[j]);
}

// combine as one K=64 GEMM (FFMA, round-14 best)
__global__ __launch_bounds__(256) void k_comb64(const float* __restrict__ sw,
                                                const float* __restrict__ sb,
                                                int l, int last) {
    __shared__ __align__(16) float Bk[64*128];
    __shared__ __align__(16) float Ak[64*32];
    int bb = blockIdx.x >> 7, h = blockIdx.x & 127;
    int e = g_idx[bb];
    int tid = threadIdx.x;

    for (int p = tid; p < 1024; p += 256) {
        int row = p >> 5, q = p & 31;
        int drow = (row == 31) ? 63 : row;
        ((float4*)(Bk + drow*128))[q] = ((const float4*)(g_Tw + row*128))[q];
    }
    for (int p = tid; p < 1024; p += 256) {
        int i = p >> 5, q = p & 31;
        ((float4*)(Bk + (31+i)*128))[q] = ((const float4*)(g_v + ((bb*32+i)*128+h)*128))[q];
    }
    for (int p = tid; p < 512; p += 256) {
        int o = p >> 4, ky = p & 15;
        float2 z = g_Z[((bb*32+o)*128+h)*16 + ky];
        const float s2 = 2.0f/16384.0f;
        if (ky == 0) Ak[o] = z.x*(1.0f/16384.0f);
        else { Ak[ky*32+o] = z.x*s2; Ak[(15+ky)*32+o] = -z.y*s2; }
    }
    for (int p = tid; p < 1024; p += 256)
        Ak[(31 + (p>>5))*32 + (p & 31)] = sw[(e*4+l)*1024 + p];
    if (tid < 32) Ak[63*32 + tid] = sb[(e*4+l)*32 + tid];
    __syncthreads();

    int wg = tid & 31, og = tid >> 5;
    float acc[4][4];
    #pragma unroll
    for (int i = 0; i < 4; i++)
        #pragma unroll
        for (int j = 0; j < 4; j++) acc[i][j] = 0.f;
    #pragma unroll 8
    for (int k = 0; k < 64; k++) {
        float4 bv = ((const float4*)(Bk + k*128))[wg];
        float4 av = ((const float4*)(Ak + k*32))[og];
        acc[0][0]+=av.x*bv.x; acc[0][1]+=av.x*bv.y; acc[0][2]+=av.x*bv.z; acc[0][3]+=av.x*bv.w;
        acc[1][0]+=av.y*bv.x; acc[1][1]+=av.y*bv.y; acc[1][2]+=av.y*bv.z; acc[1][3]+=av.y*bv.w;
        acc[2][0]+=av.z*bv.x; acc[2][1]+=av.z*bv.y; acc[2][2]+=av.z*bv.z; acc[2][3]+=av.z*bv.w;
        acc[3][0]+=av.w*bv.x; acc[3][1]+=av.w*bv.y; acc[3][2]+=av.w*bv.z; acc[3][3]+=av.w*bv.w;
    }
    #pragma unroll
    for (int i = 0; i < 4; i++) {
        int o = og*4 + i;
        float v0 = acc[i][0], v1 = acc[i][1], v2 = acc[i][2], v3 = acc[i][3];
        if (!last) { v0 = gelu_tanh(v0); v1 = gelu_tanh(v1); v2 = gelu_tanh(v2); v3 = gelu_tanh(v3); }
        ((float4*)(g_v + ((bb*32+o)*128+h)*128))[wg] = make_float4(v0, v1, v2, v3);
    }
}

// projection
__global__ __launch_bounds__(256, 2) void k_proj2(
        const float* __restrict__ p1w, const float* __restrict__ p1b,
        const float* __restrict__ p2w, const float* __restrict__ p2b,
        float* __restrict__ out) {
    __shared__ float vs [32*128];
    __shared__ float w1p[32*128];
    __shared__ float red[16*128];
    __shared__ float b1s[128], p2s[128];
    int bb = blockIdx.x >> 7, h = blockIdx.x & 127;
    int e = g_idx[bb];
    int tid = threadIdx.x;
    #pragma unroll
    for (int j = 0; j < 4; j++) {
        int p = tid + 256*j;
        int i = p >> 5, q = p & 31;
        ((float4*)(vs + i*128))[q] = ((const float4*)(g_v + ((bb*32+i)*128+h)*128))[q];
    }
    for (int p = tid; p < 4096; p += 256) {
        float val = p1w[e*4096 + p];
        int c = p >> 7, pch = p & 127;
        w1p[c*128 + (pch & 15)*8 + (pch >> 4)] = val;
    }
    if (tid < 128) {
        b1s[tid] = p1b[e*128 + tid];
        p2s[tid] = p2w[e*128 + tid];
    }
    __syncthreads();

    int wg = tid & 15, pg = tid >> 4;
    int w0 = wg*8;
    float acc[8][8];
    #pragma unroll
    for (int i = 0; i < 8; i++)
        #pragma unroll
        for (int j = 0; j < 8; j++) acc[i][j] = 0.f;
    #pragma unroll 2
    for (int c = 0; c < 32; c++) {
        float4 v0 = ((const float4*)(vs + c*128 + w0))[0];
        float4 v1 = ((const float4*)(vs + c*128 + w0))[1];
        float4 u0 = ((const float4*)(w1p + c*128 + pg*8))[0];
        float4 u1 = ((const float4*)(w1p + c*128 + pg*8))[1];
        float vv[8] = {v0.x,v0.y,v0.z,v0.w,v1.x,v1.y,v1.z,v1.w};
        float uu[8] = {u0.x,u0.y,u0.z,u0.w,u1.x,u1.y,u1.z,u1.w};
        #pragma unroll
        for (int i = 0; i < 8; i++)
            #pragma unroll
            for (int j = 0; j < 8; j++)
                acc[i][j] += uu[i]*vv[j];
    }
    float part[8];
    #pragma unroll
    for (int j = 0; j < 8; j++) part[j] = 0.f;
    #pragma unroll
    for (int i = 0; i < 8; i++) {
        int pch = pg + 16*i;
        float bias = b1s[pch], p2v = p2s[pch];
        #pragma unroll
        for (int j = 0; j < 8; j++)
            part[j] += gelu_tanh(acc[i][j] + bias)*p2v;
    }
    #pragma unroll
    for (int j = 0; j < 8; j++) red[pg*128 + w0 + j] = part[j];
    __syncthreads();
    if (tid < 128) {
        int w = tid;
        float o = p2b[e];
        #pragma unroll
        for (int pg2 = 0; pg2 < 16; pg2++) o += red[pg2*128 + w];
        out[bb*16384 + h*128 + w] = o;
    }
}

// ========================= launch =========================
extern "C" void kernel_launch(void* const* d_in, const int* in_sizes, int n_in,
                              void* d_out, int out_size) {
    const float* x        = (const float*)d_in[0];
    const float* enc_in_w = (const float*)d_in[1];
    const float* enc_in_b = (const float*)d_in[2];
    const float* qkv_w    = (const float*)d_in[3];
    const float* qkv_b    = (const float*)d_in[4];
    const float* ao_w     = (const float*)d_in[5];
    const float* ao_b     = (const float*)d_in[6];
    const float* ln1_s    = (const float*)d_in[7];
    const float* ln1_b    = (const float*)d_in[8];
    const float* ff1_w    = (const float*)d_in[9];
    const float* ff1_b    = (const float*)d_in[10];
    const float* ff2_w    = (const float*)d_in[11];
    const float* ff2_b    = (const float*)d_in[12];
    const float* ln2_s    = (const float*)d_in[13];
    const float* ln2_b    = (const float*)d_in[14];
    const float* fc_w     = (const float*)d_in[15];
    const float* fc_b     = (const float*)d_in[16];
    const float* lift_w   = (const float*)d_in[17];
    const float* lift_b   = (const float*)d_in[18];
    const float* spec_wr  = (const float*)d_in[19];
    const float* spec_wi  = (const float*)d_in[20];
    const float* skip_w   = (const float*)d_in[21];
    const float* skip_b   = (const float*)d_in[22];
    const float* p1_w     = (const float*)d_in[23];
    const float* p1_b     = (const float*)d_in[24];
    const float* p2_w     = (const float*)d_in[25];
    const float* p2_b     = (const float*)d_in[26];

    cudaFuncSetAttribute(k_dft2, cudaFuncAttributeMaxDynamicSharedMemorySize, 59392);
    cudaFuncSetAttribute(k_pro,  cudaFuncAttributeMaxDynamicSharedMemorySize, 59392);

    // fused prologue: twiddles + input 2D DFT + encode
    k_pro<<<128, 256, 59392>>>(x, enc_in_w, enc_in_b);

    // ---- router ----
    for (int l = 0; l < NENCn; l++) {
        k_attn_qkv<<<Bn*NHn, 256>>>(qkv_w, qkv_b, l);
        k_plf<<<(Bn*Sn)/16, 256>>>(ao_w, ao_b, ln1_s, ln1_b,
                                   ff1_w, ff1_b, ff2_w, ff2_b, ln2_s, ln2_b, l);
    }
    k_head<<<Bn, 128>>>(fc_w, fc_b);

    // ---- FNO ----
    k_liftx0<<<Bn*Hn + Bn, 256>>>(x, lift_w, lift_b);
    for (int l = 0; l < NLn; l++) {
        if (l > 0) k_dft2<<<Bn*CHn, 256, 59392>>>();
        k_mix<<<Bn*KXn, 256>>>(spec_wr, spec_wi, l);
        k_idft2<<<Bn*CHn, 256>>>();
        k_comb64<<<Bn*Hn, 256>>>(skip_w, skip_b, l, (l == NLn-1) ? 1 : 0);
    }
    k_proj2<<<Bn*Hn, 256>>>(p1_w, p1_b, p2_w, p2_b, (float*)d_out);
}